// round 12
// baseline (speedup 1.0000x reference)
#include <cuda_runtime.h>
#include <cuda_bf16.h>
#include <math.h>
#include <stdint.h>

// Problem constants
#define B_ 8
#define S_ 2048
#define H_ 768
#define NROW 4096                 // B_ * 512 span rows
#define SPAN_DIM 2688             // 3*H + H/2
#define SIN_DIM 2706              // SPAN_DIM + 18
#define KPAD 2752                 // K padded to multiple of 64
#define N_TYPE 18
#define N_SENS 4
#define N_BIO 3
#define WEMB_D 384

#define KITERS1 42                // 2688/64  (GEMM1: rep only)
#define KITERS2 43                // 2752/64  (GEMM2: rep + probs + zero pad)

// ---------------------------------------------------------------------------
// Static scratch (zero-initialized; pad regions never written -> stay zero)
// ---------------------------------------------------------------------------
__device__ __nv_bfloat16 g_Ahi[(size_t)NROW * KPAD];   // span reps, hi part
__device__ __nv_bfloat16 g_Alo[(size_t)NROW * KPAD];   // span reps, lo part
__device__ __nv_bfloat16 g_Bt1hi[(size_t)H_ * KPAD];   // W_t1^T hi  [768][KPAD]
__device__ __nv_bfloat16 g_Bt1lo[(size_t)H_ * KPAD];
__device__ __nv_bfloat16 g_Bs1hi[(size_t)H_ * KPAD];   // W_s1^T hi
__device__ __nv_bfloat16 g_Bs1lo[(size_t)H_ * KPAD];
__device__ float g_t[(size_t)NROW * H_];               // gelu(rep @ W_t1 + b)
__device__ float g_s[(size_t)NROW * H_];               // gelu(s_in @ W_s1 + b)

__device__ __forceinline__ float gelu_exact(float x) {
    return 0.5f * x * (1.0f + erff(x * 0.70710678118654752f));
}

__device__ __forceinline__ void bsplit(float a, __nv_bfloat16* hi, __nv_bfloat16* lo) {
    __nv_bfloat16 h = __float2bfloat16(a);
    *hi = h;
    *lo = __float2bfloat16(a - __bfloat162float(h));
}

__device__ __forceinline__ uint32_t smem_u32(const void* p) {
    uint32_t a;
    asm("{ .reg .u64 t; cvta.to.shared.u64 t, %1; cvt.u32.u64 %0, t; }" : "=r"(a) : "l"(p));
    return a;
}

__device__ __forceinline__ void cp_async16(uint32_t dst, const void* src) {
    asm volatile("cp.async.cg.shared.global [%0], [%1], 16;" :: "r"(dst), "l"(src) : "memory");
}
#define CP_COMMIT() asm volatile("cp.async.commit_group;" ::: "memory")
#define CP_WAIT(n)  asm volatile("cp.async.wait_group %0;" :: "n"(n) : "memory")

__device__ __forceinline__ void ldmx4(uint32_t* r, uint32_t addr) {
    asm volatile("ldmatrix.sync.aligned.m8n8.x4.shared.b16 {%0,%1,%2,%3}, [%4];"
                 : "=r"(r[0]), "=r"(r[1]), "=r"(r[2]), "=r"(r[3]) : "r"(addr));
}

__device__ __forceinline__ void mma_bf16(float* c, const uint32_t* a, const uint32_t* b) {
    asm volatile(
        "mma.sync.aligned.m16n8k16.row.col.f32.bf16.bf16.f32 "
        "{%0,%1,%2,%3}, {%4,%5,%6,%7}, {%8,%9}, {%0,%1,%2,%3};"
        : "+f"(c[0]), "+f"(c[1]), "+f"(c[2]), "+f"(c[3])
        : "r"(a[0]), "r"(a[1]), "r"(a[2]), "r"(a[3]), "r"(b[0]), "r"(b[1]));
}

// ---------------------------------------------------------------------------
// HMMA GEMM: C[4096,768] = gelu(A * B^T + bias), bf16x3 split, fp32 accum.
// Fused-pass mainloop: per BK=64 chunk, load Ahi/Alo/Bhi/Blo once, issue
// Ahi*Bhi + Alo*Bhi + Ahi*Blo into the same accumulators.
// CTA tile 128x128, BK=64, 3-stage cp.async pipeline, 256 threads (8 warps,
// warp tile 64x32). SW128-style swizzle: 16B chunk j at row r -> j^(r&7).
// ---------------------------------------------------------------------------
#define BMg 128
#define BNg 128
#define NSTG 3
#define OFF_AHI 0
#define OFF_ALO 16384
#define OFF_BHI 32768
#define OFF_BLO 49152
#define STG_BYTES 65536
#define GEMM_SMEM (NSTG * STG_BYTES)    // 192 KB

__global__ __launch_bounds__(256, 1)
void mma_gemm(const __nv_bfloat16* __restrict__ Ahi,
              const __nv_bfloat16* __restrict__ Alo,
              const __nv_bfloat16* __restrict__ Bhi,
              const __nv_bfloat16* __restrict__ Blo,
              const float* __restrict__ bias,
              float* __restrict__ C,
              int kiters) {
    extern __shared__ char smem[];
    const uint32_t sb = smem_u32(smem);
    const int tid = threadIdx.x;
    const int lane = tid & 31;
    const int wid = tid >> 5;
    const int warpM = wid >> 2;            // 0..1 -> 64 rows each
    const int warpN = wid & 3;             // 0..3 -> 32 cols each
    const int m0 = blockIdx.y * BMg;
    const int n0 = blockIdx.x * BNg;

    // ---- loader per-thread indices: 256 threads, 128 rows x 8 chunks/tile ----
    const int jj = tid & 7;                // 16B chunk within 128B row
    const int r0 = tid >> 3;               // 0..31
    uint32_t dstOff[4];
    #pragma unroll
    for (int q = 0; q < 4; q++) {
        int r = r0 + 32 * q;
        dstOff[q] = r * 128 + ((jj ^ (r & 7)) << 4);
    }

    // ---- ldmatrix per-lane row bases ----
    uint32_t aRowOff[4]; int aR7[4];
    const int csA = lane >> 4;
    #pragma unroll
    for (int mt = 0; mt < 4; mt++) {
        int row = warpM * 64 + mt * 16 + (lane & 7) + ((lane >> 3) & 1) * 8;
        aRowOff[mt] = row * 128;
        aR7[mt] = row & 7;
    }
    uint32_t bRowOff[2]; int bR7[2];
    const int csB = (lane >> 3) & 1;
    #pragma unroll
    for (int np = 0; np < 2; np++) {
        int n = warpN * 32 + np * 16 + (lane & 7) + ((lane >> 4) & 1) * 8;
        bRowOff[np] = n * 128;
        bR7[np] = n & 7;
    }

    float acc[4][4][4];
    #pragma unroll
    for (int i = 0; i < 4; i++)
        #pragma unroll
        for (int j = 0; j < 4; j++)
            #pragma unroll
            for (int q = 0; q < 4; q++) acc[i][j][q] = 0.f;

    auto load_stage = [&](int i) {
        const uint32_t base = sb + (uint32_t)(i % NSTG) * STG_BYTES;
        const size_t gk = (size_t)i * 64 + jj * 8;
        #pragma unroll
        for (int q = 0; q < 4; q++) {
            const size_t arow = (size_t)(m0 + r0 + 32 * q) * KPAD + gk;
            cp_async16(base + OFF_AHI + dstOff[q], Ahi + arow);
            cp_async16(base + OFF_ALO + dstOff[q], Alo + arow);
        }
        #pragma unroll
        for (int q = 0; q < 4; q++) {
            const size_t brow = (size_t)(n0 + r0 + 32 * q) * KPAD + gk;
            cp_async16(base + OFF_BHI + dstOff[q], Bhi + brow);
            cp_async16(base + OFF_BLO + dstOff[q], Blo + brow);
        }
        CP_COMMIT();
    };

    load_stage(0);
    load_stage(1);

    for (int i = 0; i < kiters; i++) {
        CP_WAIT(1);
        __syncthreads();
        if (i + 2 < kiters) load_stage(i + 2);

        const uint32_t base = sb + (uint32_t)(i % NSTG) * STG_BYTES;
        #pragma unroll
        for (int k16 = 0; k16 < 4; k16++) {
            uint32_t ah[4][4], al[4][4], bh[2][4], bl[2][4];
            #pragma unroll
            for (int mt = 0; mt < 4; mt++)
                ldmx4(ah[mt], base + OFF_AHI + aRowOff[mt] + (((k16 * 2 + csA) ^ aR7[mt]) << 4));
            #pragma unroll
            for (int np = 0; np < 2; np++)
                ldmx4(bh[np], base + OFF_BHI + bRowOff[np] + (((k16 * 2 + csB) ^ bR7[np]) << 4));
            // pass 0: Ahi * Bhi
            #pragma unroll
            for (int mt = 0; mt < 4; mt++)
                #pragma unroll
                for (int nt = 0; nt < 4; nt++)
                    mma_bf16(acc[mt][nt], ah[mt], &bh[nt >> 1][(nt & 1) * 2]);
            #pragma unroll
            for (int mt = 0; mt < 4; mt++)
                ldmx4(al[mt], base + OFF_ALO + aRowOff[mt] + (((k16 * 2 + csA) ^ aR7[mt]) << 4));
            // pass 1: Alo * Bhi
            #pragma unroll
            for (int mt = 0; mt < 4; mt++)
                #pragma unroll
                for (int nt = 0; nt < 4; nt++)
                    mma_bf16(acc[mt][nt], al[mt], &bh[nt >> 1][(nt & 1) * 2]);
            #pragma unroll
            for (int np = 0; np < 2; np++)
                ldmx4(bl[np], base + OFF_BLO + bRowOff[np] + (((k16 * 2 + csB) ^ bR7[np]) << 4));
            // pass 2: Ahi * Blo
            #pragma unroll
            for (int mt = 0; mt < 4; mt++)
                #pragma unroll
                for (int nt = 0; nt < 4; nt++)
                    mma_bf16(acc[mt][nt], ah[mt], &bl[nt >> 1][(nt & 1) * 2]);
        }
    }

    // ---- epilogue: bias + exact GELU, fp32 out ----
    #pragma unroll
    for (int mt = 0; mt < 4; mt++) {
        int row = m0 + warpM * 64 + mt * 16 + (lane >> 2);
        #pragma unroll
        for (int nt = 0; nt < 4; nt++) {
            int col = n0 + warpN * 32 + nt * 8 + (lane & 3) * 2;
            float b0 = __ldg(bias + col), b1 = __ldg(bias + col + 1);
            float2 v0, v1;
            v0.x = gelu_exact(acc[mt][nt][0] + b0);
            v0.y = gelu_exact(acc[mt][nt][1] + b1);
            v1.x = gelu_exact(acc[mt][nt][2] + b0);
            v1.y = gelu_exact(acc[mt][nt][3] + b1);
            *(float2*)(C + (size_t)row * H_ + col) = v0;
            *(float2*)(C + (size_t)(row + 8) * H_ + col) = v1;
        }
    }
}

// ---------------------------------------------------------------------------
// proposal_logits = hidden @ W_prop + b   (one warp per row)
// ---------------------------------------------------------------------------
__global__ void proposal_kernel(const float* __restrict__ hidden,
                                const float* __restrict__ W_prop,
                                const float* __restrict__ b_prop,
                                float* __restrict__ out) {
    __shared__ float sW[H_ * N_BIO];
    for (int i = threadIdx.x; i < H_ * N_BIO; i += blockDim.x) sW[i] = W_prop[i];
    __syncthreads();
    int warp = threadIdx.x >> 5, lane = threadIdx.x & 31;
    int row = blockIdx.x * 8 + warp;
    if (row >= B_ * S_) return;
    const float* h = hidden + (size_t)row * H_;
    float a0 = 0.f, a1 = 0.f, a2 = 0.f;
    for (int j = lane; j < H_; j += 32) {
        float hv = h[j];
        a0 += hv * sW[j * 3 + 0];
        a1 += hv * sW[j * 3 + 1];
        a2 += hv * sW[j * 3 + 2];
    }
    #pragma unroll
    for (int off = 16; off; off >>= 1) {
        a0 += __shfl_xor_sync(0xffffffffu, a0, off);
        a1 += __shfl_xor_sync(0xffffffffu, a1, off);
        a2 += __shfl_xor_sync(0xffffffffu, a2, off);
    }
    if (lane == 0) {
        out[row * 3 + 0] = a0 + b_prop[0];
        out[row * 3 + 1] = a1 + b_prop[1];
        out[row * 3 + 2] = a2 + b_prop[2];
    }
}

// ---------------------------------------------------------------------------
// span reps -> bf16 hi/lo directly (one block per span)
// ---------------------------------------------------------------------------
__global__ void span_rep_kernel(const float* __restrict__ hidden,
                                const int* __restrict__ spans,
                                const float* __restrict__ width_emb) {
    int row = blockIdx.x;
    int b = row >> 9;
    int s = spans[row * 2 + 0];
    int e = spans[row * 2 + 1];
    int w = e - s + 1;
    float inv_w = 1.0f / (float)w;
    const float* hb = hidden + (size_t)b * S_ * H_;
    __nv_bfloat16* hi = g_Ahi + (size_t)row * KPAD;
    __nv_bfloat16* lo = g_Alo + (size_t)row * KPAD;

    for (int i = threadIdx.x; i < H_; i += blockDim.x) {
        float sh = hb[(size_t)s * H_ + i];
        float eh = hb[(size_t)e * H_ + i];
        float acc = 0.f;
        for (int q = s; q <= e; q++) acc += hb[(size_t)q * H_ + i];
        bsplit(sh, hi + i, lo + i);
        bsplit(eh, hi + H_ + i, lo + H_ + i);
        bsplit(acc * inv_w, hi + 2 * H_ + i, lo + 2 * H_ + i);
    }
    int wc = w < 63 ? w : 63;
    for (int i = threadIdx.x; i < WEMB_D; i += blockDim.x)
        bsplit(width_emb[wc * WEMB_D + i], hi + 3 * H_ + i, lo + 3 * H_ + i);
}

// ---------------------------------------------------------------------------
// transpose + bf16 split:  W[k][768] (k < Klen) -> out_hi/lo [768][KPAD]
// ---------------------------------------------------------------------------
__global__ void transpose_split(const float* __restrict__ W, int Klen,
                                __nv_bfloat16* __restrict__ out_hi,
                                __nv_bfloat16* __restrict__ out_lo) {
    __shared__ float tile[32][33];
    int nb = blockIdx.x * 32, kb = blockIdx.y * 32;
    int x = nb + threadIdx.x;
    #pragma unroll
    for (int i = 0; i < 4; i++) {
        int k = kb + threadIdx.y + i * 8;
        tile[threadIdx.y + i * 8][threadIdx.x] = (k < Klen) ? W[(size_t)k * H_ + x] : 0.f;
    }
    __syncthreads();
    int kk = kb + threadIdx.x;
    #pragma unroll
    for (int i = 0; i < 4; i++) {
        int n = nb + threadIdx.y + i * 8;
        float v = tile[threadIdx.x][threadIdx.y + i * 8];
        bsplit(v, out_hi + (size_t)n * KPAD + kk, out_lo + (size_t)n * KPAD + kk);
    }
}

// ---------------------------------------------------------------------------
// type head: logits = g_t @ W_t2 + b; softmax probs -> A_hi/A_lo cols 2688..2705
// ---------------------------------------------------------------------------
__global__ void type_head_kernel(const float* __restrict__ W_t2,
                                 const float* __restrict__ b_t2,
                                 float* __restrict__ out_logits) {
    extern __shared__ float sW[];   // 768*18
    for (int i = threadIdx.x; i < H_ * N_TYPE; i += blockDim.x) sW[i] = W_t2[i];
    __syncthreads();
    int warp = threadIdx.x >> 5, lane = threadIdx.x & 31;
    int row = blockIdx.x * 8 + warp;
    if (row >= NROW) return;
    const float* t = g_t + (size_t)row * H_;
    float acc[N_TYPE];
    #pragma unroll
    for (int c = 0; c < N_TYPE; c++) acc[c] = 0.f;
    for (int j = lane; j < H_; j += 32) {
        float tv = t[j];
        const float* wr = sW + j * N_TYPE;
        #pragma unroll
        for (int c = 0; c < N_TYPE; c++) acc[c] = fmaf(tv, wr[c], acc[c]);
    }
    #pragma unroll
    for (int c = 0; c < N_TYPE; c++)
        #pragma unroll
        for (int off = 16; off; off >>= 1)
            acc[c] += __shfl_xor_sync(0xffffffffu, acc[c], off);
    if (lane == 0) {
        float logit[N_TYPE], mx = -1e30f;
        #pragma unroll
        for (int c = 0; c < N_TYPE; c++) { logit[c] = acc[c] + b_t2[c]; mx = fmaxf(mx, logit[c]); }
        float sum = 0.f, ex[N_TYPE];
        #pragma unroll
        for (int c = 0; c < N_TYPE; c++) { ex[c] = expf(logit[c] - mx); sum += ex[c]; }
        float inv = 1.0f / sum;
        __nv_bfloat16* hi = g_Ahi + (size_t)row * KPAD + SPAN_DIM;
        __nv_bfloat16* lo = g_Alo + (size_t)row * KPAD + SPAN_DIM;
        #pragma unroll
        for (int c = 0; c < N_TYPE; c++) {
            out_logits[row * N_TYPE + c] = logit[c];
            bsplit(ex[c] * inv, hi + c, lo + c);
        }
    }
}

// ---------------------------------------------------------------------------
// sensitivity head
// ---------------------------------------------------------------------------
__global__ void sens_head_kernel(const float* __restrict__ W_s2,
                                 const float* __restrict__ b_s2,
                                 float* __restrict__ out_logits) {
    __shared__ float sW[H_ * N_SENS];
    for (int i = threadIdx.x; i < H_ * N_SENS; i += blockDim.x) sW[i] = W_s2[i];
    __syncthreads();
    int warp = threadIdx.x >> 5, lane = threadIdx.x & 31;
    int row = blockIdx.x * 8 + warp;
    if (row >= NROW) return;
    const float* s = g_s + (size_t)row * H_;
    float acc[N_SENS];
    #pragma unroll
    for (int c = 0; c < N_SENS; c++) acc[c] = 0.f;
    for (int j = lane; j < H_; j += 32) {
        float sv = s[j];
        const float* wr = sW + j * N_SENS;
        #pragma unroll
        for (int c = 0; c < N_SENS; c++) acc[c] = fmaf(sv, wr[c], acc[c]);
    }
    #pragma unroll
    for (int c = 0; c < N_SENS; c++)
        #pragma unroll
        for (int off = 16; off; off >>= 1)
            acc[c] += __shfl_xor_sync(0xffffffffu, acc[c], off);
    if (lane == 0)
        #pragma unroll
        for (int c = 0; c < N_SENS; c++)
            out_logits[row * N_SENS + c] = acc[c] + b_s2[c];
}

// ---------------------------------------------------------------------------
// Launch
// ---------------------------------------------------------------------------
extern "C" void kernel_launch(void* const* d_in, const int* in_sizes, int n_in,
                              void* d_out, int out_size) {
    const float* hidden    = (const float*)d_in[0];
    const int*   spans     = (const int*)d_in[1];
    const float* width_emb = (const float*)d_in[2];
    const float* W_prop    = (const float*)d_in[3];
    const float* b_prop    = (const float*)d_in[4];
    const float* W_t1      = (const float*)d_in[5];
    const float* b_t1      = (const float*)d_in[6];
    const float* W_t2      = (const float*)d_in[7];
    const float* b_t2      = (const float*)d_in[8];
    const float* W_s1      = (const float*)d_in[9];
    const float* b_s1      = (const float*)d_in[10];
    const float* W_s2      = (const float*)d_in[11];
    const float* b_s2      = (const float*)d_in[12];

    float* out_prop = (float*)d_out;
    float* out_type = out_prop + (size_t)B_ * S_ * N_BIO;
    float* out_sens = out_type + (size_t)NROW * N_TYPE;

    void *ahi, *alo, *bt1h, *bt1l, *bs1h, *bs1l, *tbuf, *sbuf;
    cudaGetSymbolAddress(&ahi, g_Ahi);
    cudaGetSymbolAddress(&alo, g_Alo);
    cudaGetSymbolAddress(&bt1h, g_Bt1hi);
    cudaGetSymbolAddress(&bt1l, g_Bt1lo);
    cudaGetSymbolAddress(&bs1h, g_Bs1hi);
    cudaGetSymbolAddress(&bs1l, g_Bs1lo);
    cudaGetSymbolAddress(&tbuf, g_t);
    cudaGetSymbolAddress(&sbuf, g_s);

    cudaFuncSetAttribute(mma_gemm, cudaFuncAttributeMaxDynamicSharedMemorySize, GEMM_SMEM);
    cudaFuncSetAttribute(type_head_kernel, cudaFuncAttributeMaxDynamicSharedMemorySize,
                         H_ * N_TYPE * (int)sizeof(float));

    // 1. proposal head
    proposal_kernel<<<(B_ * S_) / 8, 256>>>(hidden, W_prop, b_prop, out_prop);
    // 2. span reps -> bf16 hi/lo
    span_rep_kernel<<<NROW, 256>>>(hidden, spans, width_emb);
    // 3. weight transposes (bf16 split)
    {
        dim3 blk(32, 8);
        dim3 g1(H_ / 32, (SPAN_DIM + 31) / 32);
        transpose_split<<<g1, blk>>>(W_t1, SPAN_DIM, (__nv_bfloat16*)bt1h, (__nv_bfloat16*)bt1l);
        dim3 g2(H_ / 32, (SIN_DIM + 31) / 32);
        transpose_split<<<g2, blk>>>(W_s1, SIN_DIM, (__nv_bfloat16*)bs1h, (__nv_bfloat16*)bs1l);
    }
    // 4. GEMM1: g_t = gelu(rep @ W_t1 + b_t1)
    {
        dim3 grid(H_ / BNg, NROW / BMg);
        mma_gemm<<<grid, 256, GEMM_SMEM>>>((const __nv_bfloat16*)ahi, (const __nv_bfloat16*)alo,
                                           (const __nv_bfloat16*)bt1h, (const __nv_bfloat16*)bt1l,
                                           b_t1, (float*)tbuf, KITERS1);
    }
    // 5. type head (+ probs appended into A hi/lo)
    type_head_kernel<<<NROW / 8, 256, H_ * N_TYPE * (int)sizeof(float)>>>(W_t2, b_t2, out_type);
    // 6. GEMM2: g_s = gelu([rep|probs] @ W_s1 + b_s1)
    {
        dim3 grid(H_ / BNg, NROW / BMg);
        mma_gemm<<<grid, 256, GEMM_SMEM>>>((const __nv_bfloat16*)ahi, (const __nv_bfloat16*)alo,
                                           (const __nv_bfloat16*)bs1h, (const __nv_bfloat16*)bs1l,
                                           b_s1, (float*)sbuf, KITERS2);
    }
    // 7. sensitivity head
    sens_head_kernel<<<NROW / 8, 256>>>(W_s2, b_s2, out_sens);
}

// round 13
// speedup vs baseline: 1.0010x; 1.0010x over previous
#include <cuda_runtime.h>
#include <cuda_bf16.h>
#include <math.h>
#include <stdint.h>

// Problem constants
#define B_ 8
#define S_ 2048
#define H_ 768
#define NROW 4096                 // B_ * 512 span rows
#define SPAN_DIM 2688             // 3*H + H/2
#define SIN_DIM 2706              // SPAN_DIM + 18
#define KPAD 2752                 // K padded to multiple of 64
#define N_TYPE 18
#define N_SENS 4
#define N_BIO 3
#define WEMB_D 384

#define KITERS1 42                // 2688/64  (GEMM1: rep only)
#define KITERS2 43                // 2752/64  (GEMM2: rep + probs + zero pad)

// ---------------------------------------------------------------------------
// Static scratch (zero-initialized; pad regions never written -> stay zero)
// ---------------------------------------------------------------------------
__device__ __nv_bfloat16 g_Ahi[(size_t)NROW * KPAD];   // span reps, hi part
__device__ __nv_bfloat16 g_Alo[(size_t)NROW * KPAD];   // span reps, lo part
__device__ __nv_bfloat16 g_Bt1hi[(size_t)H_ * KPAD];   // W_t1^T hi  [768][KPAD]
__device__ __nv_bfloat16 g_Bt1lo[(size_t)H_ * KPAD];
__device__ __nv_bfloat16 g_Bs1hi[(size_t)H_ * KPAD];   // W_s1^T hi
__device__ __nv_bfloat16 g_Bs1lo[(size_t)H_ * KPAD];
__device__ float g_t[(size_t)NROW * H_];               // gelu(rep @ W_t1 + b)
__device__ float g_s[(size_t)NROW * H_];               // gelu(s_in @ W_s1 + b)

__device__ __forceinline__ float gelu_exact(float x) {
    return 0.5f * x * (1.0f + erff(x * 0.70710678118654752f));
}

__device__ __forceinline__ void bsplit(float a, __nv_bfloat16* hi, __nv_bfloat16* lo) {
    __nv_bfloat16 h = __float2bfloat16(a);
    *hi = h;
    *lo = __float2bfloat16(a - __bfloat162float(h));
}

__device__ __forceinline__ uint32_t smem_u32(const void* p) {
    uint32_t a;
    asm("{ .reg .u64 t; cvta.to.shared.u64 t, %1; cvt.u32.u64 %0, t; }" : "=r"(a) : "l"(p));
    return a;
}

__device__ __forceinline__ void cp_async16(uint32_t dst, const void* src) {
    asm volatile("cp.async.cg.shared.global [%0], [%1], 16;" :: "r"(dst), "l"(src) : "memory");
}
#define CP_COMMIT() asm volatile("cp.async.commit_group;" ::: "memory")
#define CP_WAIT(n)  asm volatile("cp.async.wait_group %0;" :: "n"(n) : "memory")

__device__ __forceinline__ void ldmx4(uint32_t* r, uint32_t addr) {
    asm volatile("ldmatrix.sync.aligned.m8n8.x4.shared.b16 {%0,%1,%2,%3}, [%4];"
                 : "=r"(r[0]), "=r"(r[1]), "=r"(r[2]), "=r"(r[3]) : "r"(addr));
}

__device__ __forceinline__ void mma_bf16(float* c, const uint32_t* a, const uint32_t* b) {
    asm volatile(
        "mma.sync.aligned.m16n8k16.row.col.f32.bf16.bf16.f32 "
        "{%0,%1,%2,%3}, {%4,%5,%6,%7}, {%8,%9}, {%0,%1,%2,%3};"
        : "+f"(c[0]), "+f"(c[1]), "+f"(c[2]), "+f"(c[3])
        : "r"(a[0]), "r"(a[1]), "r"(a[2]), "r"(a[3]), "r"(b[0]), "r"(b[1]));
}

// ---------------------------------------------------------------------------
// HMMA GEMM: C[4096,768] = gelu(A * B^T + bias), bf16x3 split, fp32 accum.
// Fused-pass mainloop: per BK=64 chunk, load Ahi/Alo/Bhi/Blo once, issue
// Ahi*Bhi + Alo*Bhi + Ahi*Blo into the same accumulators.
// CTA tile 128x128, BK=64, 3-stage cp.async pipeline, 256 threads (8 warps,
// warp tile 64x32). SW128-style swizzle: 16B chunk j at row r -> j^(r&7).
// ---------------------------------------------------------------------------
#define BMg 128
#define BNg 128
#define NSTG 3
#define OFF_AHI 0
#define OFF_ALO 16384
#define OFF_BHI 32768
#define OFF_BLO 49152
#define STG_BYTES 65536
#define GEMM_SMEM (NSTG * STG_BYTES)    // 192 KB

__global__ __launch_bounds__(256, 1)
void mma_gemm(const __nv_bfloat16* __restrict__ Ahi,
              const __nv_bfloat16* __restrict__ Alo,
              const __nv_bfloat16* __restrict__ Bhi,
              const __nv_bfloat16* __restrict__ Blo,
              const float* __restrict__ bias,
              float* __restrict__ C,
              int kiters) {
    extern __shared__ char smem[];
    const uint32_t sb = smem_u32(smem);
    const int tid = threadIdx.x;
    const int lane = tid & 31;
    const int wid = tid >> 5;
    const int warpM = wid >> 2;            // 0..1 -> 64 rows each
    const int warpN = wid & 3;             // 0..3 -> 32 cols each
    const int m0 = blockIdx.y * BMg;
    const int n0 = blockIdx.x * BNg;

    // ---- loader per-thread indices: 256 threads, 128 rows x 8 chunks/tile ----
    const int jj = tid & 7;                // 16B chunk within 128B row
    const int r0 = tid >> 3;               // 0..31
    uint32_t dstOff[4];
    #pragma unroll
    for (int q = 0; q < 4; q++) {
        int r = r0 + 32 * q;
        dstOff[q] = r * 128 + ((jj ^ (r & 7)) << 4);
    }

    // ---- ldmatrix per-lane row bases ----
    uint32_t aRowOff[4]; int aR7[4];
    const int csA = lane >> 4;
    #pragma unroll
    for (int mt = 0; mt < 4; mt++) {
        int row = warpM * 64 + mt * 16 + (lane & 7) + ((lane >> 3) & 1) * 8;
        aRowOff[mt] = row * 128;
        aR7[mt] = row & 7;
    }
    uint32_t bRowOff[2]; int bR7[2];
    const int csB = (lane >> 3) & 1;
    #pragma unroll
    for (int np = 0; np < 2; np++) {
        int n = warpN * 32 + np * 16 + (lane & 7) + ((lane >> 4) & 1) * 8;
        bRowOff[np] = n * 128;
        bR7[np] = n & 7;
    }

    float acc[4][4][4];
    #pragma unroll
    for (int i = 0; i < 4; i++)
        #pragma unroll
        for (int j = 0; j < 4; j++)
            #pragma unroll
            for (int q = 0; q < 4; q++) acc[i][j][q] = 0.f;

    auto load_stage = [&](int i) {
        const uint32_t base = sb + (uint32_t)(i % NSTG) * STG_BYTES;
        const size_t gk = (size_t)i * 64 + jj * 8;
        #pragma unroll
        for (int q = 0; q < 4; q++) {
            const size_t arow = (size_t)(m0 + r0 + 32 * q) * KPAD + gk;
            cp_async16(base + OFF_AHI + dstOff[q], Ahi + arow);
            cp_async16(base + OFF_ALO + dstOff[q], Alo + arow);
        }
        #pragma unroll
        for (int q = 0; q < 4; q++) {
            const size_t brow = (size_t)(n0 + r0 + 32 * q) * KPAD + gk;
            cp_async16(base + OFF_BHI + dstOff[q], Bhi + brow);
            cp_async16(base + OFF_BLO + dstOff[q], Blo + brow);
        }
        CP_COMMIT();
    };

    load_stage(0);
    load_stage(1);

    for (int i = 0; i < kiters; i++) {
        CP_WAIT(1);
        __syncthreads();
        if (i + 2 < kiters) load_stage(i + 2);

        const uint32_t base = sb + (uint32_t)(i % NSTG) * STG_BYTES;
        #pragma unroll
        for (int k16 = 0; k16 < 4; k16++) {
            uint32_t ah[4][4], al[4][4], bh[2][4], bl[2][4];
            #pragma unroll
            for (int mt = 0; mt < 4; mt++)
                ldmx4(ah[mt], base + OFF_AHI + aRowOff[mt] + (((k16 * 2 + csA) ^ aR7[mt]) << 4));
            #pragma unroll
            for (int np = 0; np < 2; np++)
                ldmx4(bh[np], base + OFF_BHI + bRowOff[np] + (((k16 * 2 + csB) ^ bR7[np]) << 4));
            // pass 0: Ahi * Bhi
            #pragma unroll
            for (int mt = 0; mt < 4; mt++)
                #pragma unroll
                for (int nt = 0; nt < 4; nt++)
                    mma_bf16(acc[mt][nt], ah[mt], &bh[nt >> 1][(nt & 1) * 2]);
            #pragma unroll
            for (int mt = 0; mt < 4; mt++)
                ldmx4(al[mt], base + OFF_ALO + aRowOff[mt] + (((k16 * 2 + csA) ^ aR7[mt]) << 4));
            // pass 1: Alo * Bhi
            #pragma unroll
            for (int mt = 0; mt < 4; mt++)
                #pragma unroll
                for (int nt = 0; nt < 4; nt++)
                    mma_bf16(acc[mt][nt], al[mt], &bh[nt >> 1][(nt & 1) * 2]);
            #pragma unroll
            for (int np = 0; np < 2; np++)
                ldmx4(bl[np], base + OFF_BLO + bRowOff[np] + (((k16 * 2 + csB) ^ bR7[np]) << 4));
            // pass 2: Ahi * Blo
            #pragma unroll
            for (int mt = 0; mt < 4; mt++)
                #pragma unroll
                for (int nt = 0; nt < 4; nt++)
                    mma_bf16(acc[mt][nt], ah[mt], &bl[nt >> 1][(nt & 1) * 2]);
        }
    }

    // ---- epilogue: bias + exact GELU, fp32 out ----
    #pragma unroll
    for (int mt = 0; mt < 4; mt++) {
        int row = m0 + warpM * 64 + mt * 16 + (lane >> 2);
        #pragma unroll
        for (int nt = 0; nt < 4; nt++) {
            int col = n0 + warpN * 32 + nt * 8 + (lane & 3) * 2;
            float b0 = __ldg(bias + col), b1 = __ldg(bias + col + 1);
            float2 v0, v1;
            v0.x = gelu_exact(acc[mt][nt][0] + b0);
            v0.y = gelu_exact(acc[mt][nt][1] + b1);
            v1.x = gelu_exact(acc[mt][nt][2] + b0);
            v1.y = gelu_exact(acc[mt][nt][3] + b1);
            *(float2*)(C + (size_t)row * H_ + col) = v0;
            *(float2*)(C + (size_t)(row + 8) * H_ + col) = v1;
        }
    }
}

// ---------------------------------------------------------------------------
// proposal_logits = hidden @ W_prop + b   (one warp per row)
// ---------------------------------------------------------------------------
__global__ void proposal_kernel(const float* __restrict__ hidden,
                                const float* __restrict__ W_prop,
                                const float* __restrict__ b_prop,
                                float* __restrict__ out) {
    __shared__ float sW[H_ * N_BIO];
    for (int i = threadIdx.x; i < H_ * N_BIO; i += blockDim.x) sW[i] = W_prop[i];
    __syncthreads();
    int warp = threadIdx.x >> 5, lane = threadIdx.x & 31;
    int row = blockIdx.x * 8 + warp;
    if (row >= B_ * S_) return;
    const float* h = hidden + (size_t)row * H_;
    float a0 = 0.f, a1 = 0.f, a2 = 0.f;
    for (int j = lane; j < H_; j += 32) {
        float hv = h[j];
        a0 += hv * sW[j * 3 + 0];
        a1 += hv * sW[j * 3 + 1];
        a2 += hv * sW[j * 3 + 2];
    }
    #pragma unroll
    for (int off = 16; off; off >>= 1) {
        a0 += __shfl_xor_sync(0xffffffffu, a0, off);
        a1 += __shfl_xor_sync(0xffffffffu, a1, off);
        a2 += __shfl_xor_sync(0xffffffffu, a2, off);
    }
    if (lane == 0) {
        out[row * 3 + 0] = a0 + b_prop[0];
        out[row * 3 + 1] = a1 + b_prop[1];
        out[row * 3 + 2] = a2 + b_prop[2];
    }
}

// ---------------------------------------------------------------------------
// span reps -> bf16 hi/lo directly (one block per span)
// ---------------------------------------------------------------------------
__global__ void span_rep_kernel(const float* __restrict__ hidden,
                                const int* __restrict__ spans,
                                const float* __restrict__ width_emb) {
    int row = blockIdx.x;
    int b = row >> 9;
    int s = spans[row * 2 + 0];
    int e = spans[row * 2 + 1];
    int w = e - s + 1;
    float inv_w = 1.0f / (float)w;
    const float* hb = hidden + (size_t)b * S_ * H_;
    __nv_bfloat16* hi = g_Ahi + (size_t)row * KPAD;
    __nv_bfloat16* lo = g_Alo + (size_t)row * KPAD;

    for (int i = threadIdx.x; i < H_; i += blockDim.x) {
        float sh = hb[(size_t)s * H_ + i];
        float eh = hb[(size_t)e * H_ + i];
        float acc = 0.f;
        for (int q = s; q <= e; q++) acc += hb[(size_t)q * H_ + i];
        bsplit(sh, hi + i, lo + i);
        bsplit(eh, hi + H_ + i, lo + H_ + i);
        bsplit(acc * inv_w, hi + 2 * H_ + i, lo + 2 * H_ + i);
    }
    int wc = w < 63 ? w : 63;
    for (int i = threadIdx.x; i < WEMB_D; i += blockDim.x)
        bsplit(width_emb[wc * WEMB_D + i], hi + 3 * H_ + i, lo + 3 * H_ + i);
}

// ---------------------------------------------------------------------------
// transpose + bf16 split:  W[k][768] (k < Klen) -> out_hi/lo [768][KPAD]
// ---------------------------------------------------------------------------
__global__ void transpose_split(const float* __restrict__ W, int Klen,
                                __nv_bfloat16* __restrict__ out_hi,
                                __nv_bfloat16* __restrict__ out_lo) {
    __shared__ float tile[32][33];
    int nb = blockIdx.x * 32, kb = blockIdx.y * 32;
    int x = nb + threadIdx.x;
    #pragma unroll
    for (int i = 0; i < 4; i++) {
        int k = kb + threadIdx.y + i * 8;
        tile[threadIdx.y + i * 8][threadIdx.x] = (k < Klen) ? W[(size_t)k * H_ + x] : 0.f;
    }
    __syncthreads();
    int kk = kb + threadIdx.x;
    #pragma unroll
    for (int i = 0; i < 4; i++) {
        int n = nb + threadIdx.y + i * 8;
        float v = tile[threadIdx.x][threadIdx.y + i * 8];
        bsplit(v, out_hi + (size_t)n * KPAD + kk, out_lo + (size_t)n * KPAD + kk);
    }
}

// ---------------------------------------------------------------------------
// type head: logits = g_t @ W_t2 + b; softmax probs -> A_hi/A_lo cols 2688..2705
// ---------------------------------------------------------------------------
__global__ void type_head_kernel(const float* __restrict__ W_t2,
                                 const float* __restrict__ b_t2,
                                 float* __restrict__ out_logits) {
    extern __shared__ float sW[];   // 768*18
    for (int i = threadIdx.x; i < H_ * N_TYPE; i += blockDim.x) sW[i] = W_t2[i];
    __syncthreads();
    int warp = threadIdx.x >> 5, lane = threadIdx.x & 31;
    int row = blockIdx.x * 8 + warp;
    if (row >= NROW) return;
    const float* t = g_t + (size_t)row * H_;
    float acc[N_TYPE];
    #pragma unroll
    for (int c = 0; c < N_TYPE; c++) acc[c] = 0.f;
    for (int j = lane; j < H_; j += 32) {
        float tv = t[j];
        const float* wr = sW + j * N_TYPE;
        #pragma unroll
        for (int c = 0; c < N_TYPE; c++) acc[c] = fmaf(tv, wr[c], acc[c]);
    }
    #pragma unroll
    for (int c = 0; c < N_TYPE; c++)
        #pragma unroll
        for (int off = 16; off; off >>= 1)
            acc[c] += __shfl_xor_sync(0xffffffffu, acc[c], off);
    if (lane == 0) {
        float logit[N_TYPE], mx = -1e30f;
        #pragma unroll
        for (int c = 0; c < N_TYPE; c++) { logit[c] = acc[c] + b_t2[c]; mx = fmaxf(mx, logit[c]); }
        float sum = 0.f, ex[N_TYPE];
        #pragma unroll
        for (int c = 0; c < N_TYPE; c++) { ex[c] = expf(logit[c] - mx); sum += ex[c]; }
        float inv = 1.0f / sum;
        __nv_bfloat16* hi = g_Ahi + (size_t)row * KPAD + SPAN_DIM;
        __nv_bfloat16* lo = g_Alo + (size_t)row * KPAD + SPAN_DIM;
        #pragma unroll
        for (int c = 0; c < N_TYPE; c++) {
            out_logits[row * N_TYPE + c] = logit[c];
            bsplit(ex[c] * inv, hi + c, lo + c);
        }
    }
}

// ---------------------------------------------------------------------------
// sensitivity head
// ---------------------------------------------------------------------------
__global__ void sens_head_kernel(const float* __restrict__ W_s2,
                                 const float* __restrict__ b_s2,
                                 float* __restrict__ out_logits) {
    __shared__ float sW[H_ * N_SENS];
    for (int i = threadIdx.x; i < H_ * N_SENS; i += blockDim.x) sW[i] = W_s2[i];
    __syncthreads();
    int warp = threadIdx.x >> 5, lane = threadIdx.x & 31;
    int row = blockIdx.x * 8 + warp;
    if (row >= NROW) return;
    const float* s = g_s + (size_t)row * H_;
    float acc[N_SENS];
    #pragma unroll
    for (int c = 0; c < N_SENS; c++) acc[c] = 0.f;
    for (int j = lane; j < H_; j += 32) {
        float sv = s[j];
        const float* wr = sW + j * N_SENS;
        #pragma unroll
        for (int c = 0; c < N_SENS; c++) acc[c] = fmaf(sv, wr[c], acc[c]);
    }
    #pragma unroll
    for (int c = 0; c < N_SENS; c++)
        #pragma unroll
        for (int off = 16; off; off >>= 1)
            acc[c] += __shfl_xor_sync(0xffffffffu, acc[c], off);
    if (lane == 0)
        #pragma unroll
        for (int c = 0; c < N_SENS; c++)
            out_logits[row * N_SENS + c] = acc[c] + b_s2[c];
}

// ---------------------------------------------------------------------------
// Launch
// ---------------------------------------------------------------------------
extern "C" void kernel_launch(void* const* d_in, const int* in_sizes, int n_in,
                              void* d_out, int out_size) {
    const float* hidden    = (const float*)d_in[0];
    const int*   spans     = (const int*)d_in[1];
    const float* width_emb = (const float*)d_in[2];
    const float* W_prop    = (const float*)d_in[3];
    const float* b_prop    = (const float*)d_in[4];
    const float* W_t1      = (const float*)d_in[5];
    const float* b_t1      = (const float*)d_in[6];
    const float* W_t2      = (const float*)d_in[7];
    const float* b_t2      = (const float*)d_in[8];
    const float* W_s1      = (const float*)d_in[9];
    const float* b_s1      = (const float*)d_in[10];
    const float* W_s2      = (const float*)d_in[11];
    const float* b_s2      = (const float*)d_in[12];

    float* out_prop = (float*)d_out;
    float* out_type = out_prop + (size_t)B_ * S_ * N_BIO;
    float* out_sens = out_type + (size_t)NROW * N_TYPE;

    void *ahi, *alo, *bt1h, *bt1l, *bs1h, *bs1l, *tbuf, *sbuf;
    cudaGetSymbolAddress(&ahi, g_Ahi);
    cudaGetSymbolAddress(&alo, g_Alo);
    cudaGetSymbolAddress(&bt1h, g_Bt1hi);
    cudaGetSymbolAddress(&bt1l, g_Bt1lo);
    cudaGetSymbolAddress(&bs1h, g_Bs1hi);
    cudaGetSymbolAddress(&bs1l, g_Bs1lo);
    cudaGetSymbolAddress(&tbuf, g_t);
    cudaGetSymbolAddress(&sbuf, g_s);

    cudaFuncSetAttribute(mma_gemm, cudaFuncAttributeMaxDynamicSharedMemorySize, GEMM_SMEM);
    cudaFuncSetAttribute(type_head_kernel, cudaFuncAttributeMaxDynamicSharedMemorySize,
                         H_ * N_TYPE * (int)sizeof(float));

    // 1. proposal head
    proposal_kernel<<<(B_ * S_) / 8, 256>>>(hidden, W_prop, b_prop, out_prop);
    // 2. span reps -> bf16 hi/lo
    span_rep_kernel<<<NROW, 256>>>(hidden, spans, width_emb);
    // 3. weight transposes (bf16 split)
    {
        dim3 blk(32, 8);
        dim3 g1(H_ / 32, (SPAN_DIM + 31) / 32);
        transpose_split<<<g1, blk>>>(W_t1, SPAN_DIM, (__nv_bfloat16*)bt1h, (__nv_bfloat16*)bt1l);
        dim3 g2(H_ / 32, (SIN_DIM + 31) / 32);
        transpose_split<<<g2, blk>>>(W_s1, SIN_DIM, (__nv_bfloat16*)bs1h, (__nv_bfloat16*)bs1l);
    }
    // 4. GEMM1: g_t = gelu(rep @ W_t1 + b_t1)
    {
        dim3 grid(H_ / BNg, NROW / BMg);
        mma_gemm<<<grid, 256, GEMM_SMEM>>>((const __nv_bfloat16*)ahi, (const __nv_bfloat16*)alo,
                                           (const __nv_bfloat16*)bt1h, (const __nv_bfloat16*)bt1l,
                                           b_t1, (float*)tbuf, KITERS1);
    }
    // 5. type head (+ probs appended into A hi/lo)
    type_head_kernel<<<NROW / 8, 256, H_ * N_TYPE * (int)sizeof(float)>>>(W_t2, b_t2, out_type);
    // 6. GEMM2: g_s = gelu([rep|probs] @ W_s1 + b_s1)
    {
        dim3 grid(H_ / BNg, NROW / BMg);
        mma_gemm<<<grid, 256, GEMM_SMEM>>>((const __nv_bfloat16*)ahi, (const __nv_bfloat16*)alo,
                                           (const __nv_bfloat16*)bs1h, (const __nv_bfloat16*)bs1l,
                                           b_s1, (float*)sbuf, KITERS2);
    }
    // 7. sensitivity head
    sens_head_kernel<<<NROW / 8, 256>>>(W_s2, b_s2, out_sens);
}

// round 14
// speedup vs baseline: 1.0047x; 1.0037x over previous
#include <cuda_runtime.h>
#include <cuda_bf16.h>
#include <math.h>
#include <stdint.h>

// Problem constants
#define B_ 8
#define S_ 2048
#define H_ 768
#define NROW 4096                 // B_ * 512 span rows
#define SPAN_DIM 2688             // 3*H + H/2
#define SIN_DIM 2706              // SPAN_DIM + 18
#define KPAD 2752                 // K padded to multiple of 64
#define N_TYPE 18
#define N_SENS 4
#define N_BIO 3
#define WEMB_D 384

#define KITERS1 42                // 2688/64  (GEMM1: rep only)
#define KITERS2 43                // 2752/64  (GEMM2: rep + probs + zero pad)

// ---------------------------------------------------------------------------
// Static scratch (zero-initialized; pad regions never written -> stay zero)
// ---------------------------------------------------------------------------
__device__ __nv_bfloat16 g_Ahi[(size_t)NROW * KPAD];   // span reps, hi part
__device__ __nv_bfloat16 g_Alo[(size_t)NROW * KPAD];   // span reps, lo part
__device__ __nv_bfloat16 g_Bt1hi[(size_t)H_ * KPAD];   // W_t1^T hi  [768][KPAD]
__device__ __nv_bfloat16 g_Bt1lo[(size_t)H_ * KPAD];
__device__ __nv_bfloat16 g_Bs1hi[(size_t)H_ * KPAD];   // W_s1^T hi
__device__ __nv_bfloat16 g_Bs1lo[(size_t)H_ * KPAD];
__device__ float g_t[(size_t)NROW * H_];               // gelu(rep @ W_t1 + b)
__device__ float g_s[(size_t)NROW * H_];               // gelu(s_in @ W_s1 + b)

__device__ __forceinline__ float gelu_exact(float x) {
    return 0.5f * x * (1.0f + erff(x * 0.70710678118654752f));
}

__device__ __forceinline__ void bsplit(float a, __nv_bfloat16* hi, __nv_bfloat16* lo) {
    __nv_bfloat16 h = __float2bfloat16(a);
    *hi = h;
    *lo = __float2bfloat16(a - __bfloat162float(h));
}

__device__ __forceinline__ uint32_t smem_u32(const void* p) {
    uint32_t a;
    asm("{ .reg .u64 t; cvta.to.shared.u64 t, %1; cvt.u32.u64 %0, t; }" : "=r"(a) : "l"(p));
    return a;
}

__device__ __forceinline__ void cp_async16(uint32_t dst, const void* src) {
    asm volatile("cp.async.cg.shared.global [%0], [%1], 16;" :: "r"(dst), "l"(src) : "memory");
}
#define CP_COMMIT() asm volatile("cp.async.commit_group;" ::: "memory")
#define CP_WAIT(n)  asm volatile("cp.async.wait_group %0;" :: "n"(n) : "memory")

__device__ __forceinline__ void ldmx4(uint32_t* r, uint32_t addr) {
    asm volatile("ldmatrix.sync.aligned.m8n8.x4.shared.b16 {%0,%1,%2,%3}, [%4];"
                 : "=r"(r[0]), "=r"(r[1]), "=r"(r[2]), "=r"(r[3]) : "r"(addr));
}

__device__ __forceinline__ void mma_bf16(float* c, const uint32_t* a, const uint32_t* b) {
    asm volatile(
        "mma.sync.aligned.m16n8k16.row.col.f32.bf16.bf16.f32 "
        "{%0,%1,%2,%3}, {%4,%5,%6,%7}, {%8,%9}, {%0,%1,%2,%3};"
        : "+f"(c[0]), "+f"(c[1]), "+f"(c[2]), "+f"(c[3])
        : "r"(a[0]), "r"(a[1]), "r"(a[2]), "r"(a[3]), "r"(b[0]), "r"(b[1]));
}

// ---------------------------------------------------------------------------
// HMMA GEMM: C[4096,768] = gelu(A * B^T + bias), bf16x3 split, fp32 accum.
// Fused-pass mainloop: per BK=64 chunk, load Ahi/Alo/Bhi/Blo once, issue
// Ahi*Bhi + Alo*Bhi + Ahi*Blo into the same accumulators.
// CTA tile 128x128, BK=64, 3-stage cp.async pipeline, 256 threads (8 warps,
// warp tile 64x32). SW128-style swizzle: 16B chunk j at row r -> j^(r&7).
// ---------------------------------------------------------------------------
#define BMg 128
#define BNg 128
#define NSTG 3
#define OFF_AHI 0
#define OFF_ALO 16384
#define OFF_BHI 32768
#define OFF_BLO 49152
#define STG_BYTES 65536
#define GEMM_SMEM (NSTG * STG_BYTES)    // 192 KB

__global__ __launch_bounds__(256, 1)
void mma_gemm(const __nv_bfloat16* __restrict__ Ahi,
              const __nv_bfloat16* __restrict__ Alo,
              const __nv_bfloat16* __restrict__ Bhi,
              const __nv_bfloat16* __restrict__ Blo,
              const float* __restrict__ bias,
              float* __restrict__ C,
              int kiters) {
    extern __shared__ char smem[];
    const uint32_t sb = smem_u32(smem);
    const int tid = threadIdx.x;
    const int lane = tid & 31;
    const int wid = tid >> 5;
    const int warpM = wid >> 2;            // 0..1 -> 64 rows each
    const int warpN = wid & 3;             // 0..3 -> 32 cols each
    const int m0 = blockIdx.y * BMg;
    const int n0 = blockIdx.x * BNg;

    // ---- loader per-thread indices: 256 threads, 128 rows x 8 chunks/tile ----
    const int jj = tid & 7;                // 16B chunk within 128B row
    const int r0 = tid >> 3;               // 0..31
    uint32_t dstOff[4];
    #pragma unroll
    for (int q = 0; q < 4; q++) {
        int r = r0 + 32 * q;
        dstOff[q] = r * 128 + ((jj ^ (r & 7)) << 4);
    }

    // ---- ldmatrix per-lane row bases ----
    uint32_t aRowOff[4]; int aR7[4];
    const int csA = lane >> 4;
    #pragma unroll
    for (int mt = 0; mt < 4; mt++) {
        int row = warpM * 64 + mt * 16 + (lane & 7) + ((lane >> 3) & 1) * 8;
        aRowOff[mt] = row * 128;
        aR7[mt] = row & 7;
    }
    uint32_t bRowOff[2]; int bR7[2];
    const int csB = (lane >> 3) & 1;
    #pragma unroll
    for (int np = 0; np < 2; np++) {
        int n = warpN * 32 + np * 16 + (lane & 7) + ((lane >> 4) & 1) * 8;
        bRowOff[np] = n * 128;
        bR7[np] = n & 7;
    }

    float acc[4][4][4];
    #pragma unroll
    for (int i = 0; i < 4; i++)
        #pragma unroll
        for (int j = 0; j < 4; j++)
            #pragma unroll
            for (int q = 0; q < 4; q++) acc[i][j][q] = 0.f;

    auto load_stage = [&](int i) {
        const uint32_t base = sb + (uint32_t)(i % NSTG) * STG_BYTES;
        const size_t gk = (size_t)i * 64 + jj * 8;
        #pragma unroll
        for (int q = 0; q < 4; q++) {
            const size_t arow = (size_t)(m0 + r0 + 32 * q) * KPAD + gk;
            cp_async16(base + OFF_AHI + dstOff[q], Ahi + arow);
            cp_async16(base + OFF_ALO + dstOff[q], Alo + arow);
        }
        #pragma unroll
        for (int q = 0; q < 4; q++) {
            const size_t brow = (size_t)(n0 + r0 + 32 * q) * KPAD + gk;
            cp_async16(base + OFF_BHI + dstOff[q], Bhi + brow);
            cp_async16(base + OFF_BLO + dstOff[q], Blo + brow);
        }
        CP_COMMIT();
    };

    load_stage(0);
    load_stage(1);

    for (int i = 0; i < kiters; i++) {
        CP_WAIT(1);
        __syncthreads();
        if (i + 2 < kiters) load_stage(i + 2);

        const uint32_t base = sb + (uint32_t)(i % NSTG) * STG_BYTES;
        #pragma unroll
        for (int k16 = 0; k16 < 4; k16++) {
            uint32_t ah[4][4], al[4][4], bh[2][4], bl[2][4];
            #pragma unroll
            for (int mt = 0; mt < 4; mt++)
                ldmx4(ah[mt], base + OFF_AHI + aRowOff[mt] + (((k16 * 2 + csA) ^ aR7[mt]) << 4));
            #pragma unroll
            for (int np = 0; np < 2; np++)
                ldmx4(bh[np], base + OFF_BHI + bRowOff[np] + (((k16 * 2 + csB) ^ bR7[np]) << 4));
            // pass 0: Ahi * Bhi
            #pragma unroll
            for (int mt = 0; mt < 4; mt++)
                #pragma unroll
                for (int nt = 0; nt < 4; nt++)
                    mma_bf16(acc[mt][nt], ah[mt], &bh[nt >> 1][(nt & 1) * 2]);
            #pragma unroll
            for (int mt = 0; mt < 4; mt++)
                ldmx4(al[mt], base + OFF_ALO + aRowOff[mt] + (((k16 * 2 + csA) ^ aR7[mt]) << 4));
            // pass 1: Alo * Bhi
            #pragma unroll
            for (int mt = 0; mt < 4; mt++)
                #pragma unroll
                for (int nt = 0; nt < 4; nt++)
                    mma_bf16(acc[mt][nt], al[mt], &bh[nt >> 1][(nt & 1) * 2]);
            #pragma unroll
            for (int np = 0; np < 2; np++)
                ldmx4(bl[np], base + OFF_BLO + bRowOff[np] + (((k16 * 2 + csB) ^ bR7[np]) << 4));
            // pass 2: Ahi * Blo
            #pragma unroll
            for (int mt = 0; mt < 4; mt++)
                #pragma unroll
                for (int nt = 0; nt < 4; nt++)
                    mma_bf16(acc[mt][nt], ah[mt], &bl[nt >> 1][(nt & 1) * 2]);
        }
    }

    // ---- epilogue: bias + exact GELU, fp32 out ----
    #pragma unroll
    for (int mt = 0; mt < 4; mt++) {
        int row = m0 + warpM * 64 + mt * 16 + (lane >> 2);
        #pragma unroll
        for (int nt = 0; nt < 4; nt++) {
            int col = n0 + warpN * 32 + nt * 8 + (lane & 3) * 2;
            float b0 = __ldg(bias + col), b1 = __ldg(bias + col + 1);
            float2 v0, v1;
            v0.x = gelu_exact(acc[mt][nt][0] + b0);
            v0.y = gelu_exact(acc[mt][nt][1] + b1);
            v1.x = gelu_exact(acc[mt][nt][2] + b0);
            v1.y = gelu_exact(acc[mt][nt][3] + b1);
            *(float2*)(C + (size_t)row * H_ + col) = v0;
            *(float2*)(C + (size_t)(row + 8) * H_ + col) = v1;
        }
    }
}

// ---------------------------------------------------------------------------
// proposal_logits = hidden @ W_prop + b   (one warp per row)
// ---------------------------------------------------------------------------
__global__ void proposal_kernel(const float* __restrict__ hidden,
                                const float* __restrict__ W_prop,
                                const float* __restrict__ b_prop,
                                float* __restrict__ out) {
    __shared__ float sW[H_ * N_BIO];
    for (int i = threadIdx.x; i < H_ * N_BIO; i += blockDim.x) sW[i] = W_prop[i];
    __syncthreads();
    int warp = threadIdx.x >> 5, lane = threadIdx.x & 31;
    int row = blockIdx.x * 8 + warp;
    if (row >= B_ * S_) return;
    const float* h = hidden + (size_t)row * H_;
    float a0 = 0.f, a1 = 0.f, a2 = 0.f;
    for (int j = lane; j < H_; j += 32) {
        float hv = h[j];
        a0 += hv * sW[j * 3 + 0];
        a1 += hv * sW[j * 3 + 1];
        a2 += hv * sW[j * 3 + 2];
    }
    #pragma unroll
    for (int off = 16; off; off >>= 1) {
        a0 += __shfl_xor_sync(0xffffffffu, a0, off);
        a1 += __shfl_xor_sync(0xffffffffu, a1, off);
        a2 += __shfl_xor_sync(0xffffffffu, a2, off);
    }
    if (lane == 0) {
        out[row * 3 + 0] = a0 + b_prop[0];
        out[row * 3 + 1] = a1 + b_prop[1];
        out[row * 3 + 2] = a2 + b_prop[2];
    }
}

// ---------------------------------------------------------------------------
// span reps -> bf16 hi/lo directly (one block per span)
// ---------------------------------------------------------------------------
__global__ void span_rep_kernel(const float* __restrict__ hidden,
                                const int* __restrict__ spans,
                                const float* __restrict__ width_emb) {
    int row = blockIdx.x;
    int b = row >> 9;
    int s = spans[row * 2 + 0];
    int e = spans[row * 2 + 1];
    int w = e - s + 1;
    float inv_w = 1.0f / (float)w;
    const float* hb = hidden + (size_t)b * S_ * H_;
    __nv_bfloat16* hi = g_Ahi + (size_t)row * KPAD;
    __nv_bfloat16* lo = g_Alo + (size_t)row * KPAD;

    for (int i = threadIdx.x; i < H_; i += blockDim.x) {
        float sh = hb[(size_t)s * H_ + i];
        float eh = hb[(size_t)e * H_ + i];
        float acc = 0.f;
        for (int q = s; q <= e; q++) acc += hb[(size_t)q * H_ + i];
        bsplit(sh, hi + i, lo + i);
        bsplit(eh, hi + H_ + i, lo + H_ + i);
        bsplit(acc * inv_w, hi + 2 * H_ + i, lo + 2 * H_ + i);
    }
    int wc = w < 63 ? w : 63;
    for (int i = threadIdx.x; i < WEMB_D; i += blockDim.x)
        bsplit(width_emb[wc * WEMB_D + i], hi + 3 * H_ + i, lo + 3 * H_ + i);
}

// ---------------------------------------------------------------------------
// transpose + bf16 split:  W[k][768] (k < Klen) -> out_hi/lo [768][KPAD]
// ---------------------------------------------------------------------------
__global__ void transpose_split(const float* __restrict__ W, int Klen,
                                __nv_bfloat16* __restrict__ out_hi,
                                __nv_bfloat16* __restrict__ out_lo) {
    __shared__ float tile[32][33];
    int nb = blockIdx.x * 32, kb = blockIdx.y * 32;
    int x = nb + threadIdx.x;
    #pragma unroll
    for (int i = 0; i < 4; i++) {
        int k = kb + threadIdx.y + i * 8;
        tile[threadIdx.y + i * 8][threadIdx.x] = (k < Klen) ? W[(size_t)k * H_ + x] : 0.f;
    }
    __syncthreads();
    int kk = kb + threadIdx.x;
    #pragma unroll
    for (int i = 0; i < 4; i++) {
        int n = nb + threadIdx.y + i * 8;
        float v = tile[threadIdx.x][threadIdx.y + i * 8];
        bsplit(v, out_hi + (size_t)n * KPAD + kk, out_lo + (size_t)n * KPAD + kk);
    }
}

// ---------------------------------------------------------------------------
// type head: logits = g_t @ W_t2 + b; softmax probs -> A_hi/A_lo cols 2688..2705
// ---------------------------------------------------------------------------
__global__ void type_head_kernel(const float* __restrict__ W_t2,
                                 const float* __restrict__ b_t2,
                                 float* __restrict__ out_logits) {
    extern __shared__ float sW[];   // 768*18
    for (int i = threadIdx.x; i < H_ * N_TYPE; i += blockDim.x) sW[i] = W_t2[i];
    __syncthreads();
    int warp = threadIdx.x >> 5, lane = threadIdx.x & 31;
    int row = blockIdx.x * 8 + warp;
    if (row >= NROW) return;
    const float* t = g_t + (size_t)row * H_;
    float acc[N_TYPE];
    #pragma unroll
    for (int c = 0; c < N_TYPE; c++) acc[c] = 0.f;
    for (int j = lane; j < H_; j += 32) {
        float tv = t[j];
        const float* wr = sW + j * N_TYPE;
        #pragma unroll
        for (int c = 0; c < N_TYPE; c++) acc[c] = fmaf(tv, wr[c], acc[c]);
    }
    #pragma unroll
    for (int c = 0; c < N_TYPE; c++)
        #pragma unroll
        for (int off = 16; off; off >>= 1)
            acc[c] += __shfl_xor_sync(0xffffffffu, acc[c], off);
    if (lane == 0) {
        float logit[N_TYPE], mx = -1e30f;
        #pragma unroll
        for (int c = 0; c < N_TYPE; c++) { logit[c] = acc[c] + b_t2[c]; mx = fmaxf(mx, logit[c]); }
        float sum = 0.f, ex[N_TYPE];
        #pragma unroll
        for (int c = 0; c < N_TYPE; c++) { ex[c] = expf(logit[c] - mx); sum += ex[c]; }
        float inv = 1.0f / sum;
        __nv_bfloat16* hi = g_Ahi + (size_t)row * KPAD + SPAN_DIM;
        __nv_bfloat16* lo = g_Alo + (size_t)row * KPAD + SPAN_DIM;
        #pragma unroll
        for (int c = 0; c < N_TYPE; c++) {
            out_logits[row * N_TYPE + c] = logit[c];
            bsplit(ex[c] * inv, hi + c, lo + c);
        }
    }
}

// ---------------------------------------------------------------------------
// sensitivity head
// ---------------------------------------------------------------------------
__global__ void sens_head_kernel(const float* __restrict__ W_s2,
                                 const float* __restrict__ b_s2,
                                 float* __restrict__ out_logits) {
    __shared__ float sW[H_ * N_SENS];
    for (int i = threadIdx.x; i < H_ * N_SENS; i += blockDim.x) sW[i] = W_s2[i];
    __syncthreads();
    int warp = threadIdx.x >> 5, lane = threadIdx.x & 31;
    int row = blockIdx.x * 8 + warp;
    if (row >= NROW) return;
    const float* s = g_s + (size_t)row * H_;
    float acc[N_SENS];
    #pragma unroll
    for (int c = 0; c < N_SENS; c++) acc[c] = 0.f;
    for (int j = lane; j < H_; j += 32) {
        float sv = s[j];
        const float* wr = sW + j * N_SENS;
        #pragma unroll
        for (int c = 0; c < N_SENS; c++) acc[c] = fmaf(sv, wr[c], acc[c]);
    }
    #pragma unroll
    for (int c = 0; c < N_SENS; c++)
        #pragma unroll
        for (int off = 16; off; off >>= 1)
            acc[c] += __shfl_xor_sync(0xffffffffu, acc[c], off);
    if (lane == 0)
        #pragma unroll
        for (int c = 0; c < N_SENS; c++)
            out_logits[row * N_SENS + c] = acc[c] + b_s2[c];
}

// ---------------------------------------------------------------------------
// Launch
// ---------------------------------------------------------------------------
extern "C" void kernel_launch(void* const* d_in, const int* in_sizes, int n_in,
                              void* d_out, int out_size) {
    const float* hidden    = (const float*)d_in[0];
    const int*   spans     = (const int*)d_in[1];
    const float* width_emb = (const float*)d_in[2];
    const float* W_prop    = (const float*)d_in[3];
    const float* b_prop    = (const float*)d_in[4];
    const float* W_t1      = (const float*)d_in[5];
    const float* b_t1      = (const float*)d_in[6];
    const float* W_t2      = (const float*)d_in[7];
    const float* b_t2      = (const float*)d_in[8];
    const float* W_s1      = (const float*)d_in[9];
    const float* b_s1      = (const float*)d_in[10];
    const float* W_s2      = (const float*)d_in[11];
    const float* b_s2      = (const float*)d_in[12];

    float* out_prop = (float*)d_out;
    float* out_type = out_prop + (size_t)B_ * S_ * N_BIO;
    float* out_sens = out_type + (size_t)NROW * N_TYPE;

    void *ahi, *alo, *bt1h, *bt1l, *bs1h, *bs1l, *tbuf, *sbuf;
    cudaGetSymbolAddress(&ahi, g_Ahi);
    cudaGetSymbolAddress(&alo, g_Alo);
    cudaGetSymbolAddress(&bt1h, g_Bt1hi);
    cudaGetSymbolAddress(&bt1l, g_Bt1lo);
    cudaGetSymbolAddress(&bs1h, g_Bs1hi);
    cudaGetSymbolAddress(&bs1l, g_Bs1lo);
    cudaGetSymbolAddress(&tbuf, g_t);
    cudaGetSymbolAddress(&sbuf, g_s);

    cudaFuncSetAttribute(mma_gemm, cudaFuncAttributeMaxDynamicSharedMemorySize, GEMM_SMEM);
    cudaFuncSetAttribute(type_head_kernel, cudaFuncAttributeMaxDynamicSharedMemorySize,
                         H_ * N_TYPE * (int)sizeof(float));

    // 1. proposal head
    proposal_kernel<<<(B_ * S_) / 8, 256>>>(hidden, W_prop, b_prop, out_prop);
    // 2. span reps -> bf16 hi/lo
    span_rep_kernel<<<NROW, 256>>>(hidden, spans, width_emb);
    // 3. weight transposes (bf16 split)
    {
        dim3 blk(32, 8);
        dim3 g1(H_ / 32, (SPAN_DIM + 31) / 32);
        transpose_split<<<g1, blk>>>(W_t1, SPAN_DIM, (__nv_bfloat16*)bt1h, (__nv_bfloat16*)bt1l);
        dim3 g2(H_ / 32, (SIN_DIM + 31) / 32);
        transpose_split<<<g2, blk>>>(W_s1, SIN_DIM, (__nv_bfloat16*)bs1h, (__nv_bfloat16*)bs1l);
    }
    // 4. GEMM1: g_t = gelu(rep @ W_t1 + b_t1)
    {
        dim3 grid(H_ / BNg, NROW / BMg);
        mma_gemm<<<grid, 256, GEMM_SMEM>>>((const __nv_bfloat16*)ahi, (const __nv_bfloat16*)alo,
                                           (const __nv_bfloat16*)bt1h, (const __nv_bfloat16*)bt1l,
                                           b_t1, (float*)tbuf, KITERS1);
    }
    // 5. type head (+ probs appended into A hi/lo)
    type_head_kernel<<<NROW / 8, 256, H_ * N_TYPE * (int)sizeof(float)>>>(W_t2, b_t2, out_type);
    // 6. GEMM2: g_s = gelu([rep|probs] @ W_s1 + b_s1)
    {
        dim3 grid(H_ / BNg, NROW / BMg);
        mma_gemm<<<grid, 256, GEMM_SMEM>>>((const __nv_bfloat16*)ahi, (const __nv_bfloat16*)alo,
                                           (const __nv_bfloat16*)bs1h, (const __nv_bfloat16*)bs1l,
                                           b_s1, (float*)sbuf, KITERS2);
    }
    // 7. sensitivity head
    sens_head_kernel<<<NROW / 8, 256>>>(W_s2, b_s2, out_sens);
}